// round 1
// baseline (speedup 1.0000x reference)
#include <cuda_runtime.h>

#define TD    512   // timesteps
#define BD    512   // batch
#define HID   32    // hidden
#define G4    128   // 4*HID gate rows
#define EMBD  32
#define VOCAB 1000
#define FF    16
#define NCLS  7

// ---------------- scratch (static device globals; no runtime allocation) ----
__device__ float g_table[VOCAB * G4];                       // 512 KB gate table
__device__ float g_hs[(size_t)BD * TD * HID];               // 33.5 MB, layout (B,T,H)

// ---------------- packed f32x2 helpers -------------------------------------
__device__ __forceinline__ unsigned long long pk(float lo, float hi) {
    unsigned long long r;
    asm("mov.b64 %0, {%1,%2};" : "=l"(r) : "f"(lo), "f"(hi));
    return r;
}
__device__ __forceinline__ void upk(unsigned long long p, float& lo, float& hi) {
    asm("mov.b64 {%0,%1}, %2;" : "=f"(lo), "=f"(hi) : "l"(p));
}
__device__ __forceinline__ unsigned long long fma2(unsigned long long a,
                                                   unsigned long long b,
                                                   unsigned long long c) {
    unsigned long long d;
    asm("fma.rn.f32x2 %0, %1, %2, %3;" : "=l"(d) : "l"(a), "l"(b), "l"(c));
    return d;
}
__device__ __forceinline__ unsigned long long mul2(unsigned long long a,
                                                   unsigned long long b) {
    unsigned long long d;
    asm("mul.rn.f32x2 %0, %1, %2;" : "=l"(d) : "l"(a), "l"(b));
    return d;
}
__device__ __forceinline__ float tanh_ap(float x) {
    float y;
    asm("tanh.approx.f32 %0, %1;" : "=f"(y) : "f"(x));
    return y;
}
__device__ __forceinline__ unsigned long long tanh2(unsigned long long p) {
    float a, b; upk(p, a, b);
    return pk(tanh_ap(a), tanh_ap(b));
}
// sigmoid(x) = 0.5*tanh(0.5x) + 0.5  (1 MUFU per element instead of 2)
#define HALF2 0x3F0000003F000000ULL
__device__ __forceinline__ unsigned long long sigmoid2(unsigned long long p) {
    unsigned long long t = tanh2(mul2(p, HALF2));
    return fma2(t, HALF2, HALF2);
}

// ---------------- K0: gate table  table[v][g] = emb[v]·W_ih[g] + b_ih + b_hh
__global__ void table_kernel(const float* __restrict__ emb,
                             const float* __restrict__ W_ih,
                             const float* __restrict__ b_ih,
                             const float* __restrict__ b_hh) {
    int v = blockIdx.x;          // 0..VOCAB-1
    int r = threadIdx.x;         // 0..127
    __shared__ float e[EMBD];
    if (r < EMBD) e[r] = emb[v * EMBD + r];
    __syncthreads();
    float acc = b_ih[r] + b_hh[r];
#pragma unroll
    for (int k = 0; k < EMBD; k++) acc += W_ih[r * EMBD + k] * e[k];
    g_table[v * G4 + r] = acc;
}

// ---------------- K1: LSTM recurrence, f32x2 over batch pairs ---------------
// Grid: BD/4 CTAs x 256 threads. Each 128-thread group = 2 batch elements.
// Thread layout within group: gate = wt&3, unit = wt>>2  (gate quads within a
// warp -> c/h update via 4-lane shfl, one __syncthreads per step via
// double-buffered h in smem).
__global__ __launch_bounds__(256, 1)
void lstm_kernel(const int* __restrict__ x, const float* __restrict__ W_hh) {
    __shared__ __align__(16) unsigned long long hbuf[2][2][HID]; // [grp][parity][unit]
    int tid  = threadIdx.x;
    int grp  = tid >> 7;
    int wt   = tid & 127;
    int gate = wt & 3;
    int unit = wt >> 2;
    int wrow = gate * HID + unit;          // PyTorch gate order rows: i,f,g,o
    int b0   = blockIdx.x * 4 + grp * 2;
    int b1   = b0 + 1;

    // W_hh row, packed (w,w)
    unsigned long long Wp[HID];
#pragma unroll
    for (int k = 0; k < HID; k++) {
        float w = W_hh[wrow * HID + k];
        Wp[k] = pk(w, w);
    }

    if (wt < HID) { hbuf[grp][0][wt] = 0ull; hbuf[grp][1][wt] = 0ull; }
    unsigned long long c2 = 0ull;

    // index pipeline (depth 3) + xg pipeline (depth 2) to hide L2 latency
    int i0a = x[0 * BD + b0], i0b = x[0 * BD + b1];
    int i1a = x[1 * BD + b0], i1b = x[1 * BD + b1];
    int I2a = x[2 * BD + b0], I2b = x[2 * BD + b1];
    int I3a = x[3 * BD + b0], I3b = x[3 * BD + b1];
    int I4a = x[4 * BD + b0], I4b = x[4 * BD + b1];
    unsigned long long XG0 = pk(g_table[i0a * G4 + wrow], g_table[i0b * G4 + wrow]);
    unsigned long long XG1 = pk(g_table[i1a * G4 + wrow], g_table[i1b * G4 + wrow]);

    float* hsA = g_hs + (size_t)b0 * TD * HID;
    float* hsB = g_hs + (size_t)b1 * TD * HID;
    int lbase = (wt & 31) & ~3;   // lane base of this unit's gate quad
    __syncthreads();

    for (int t = 0; t < TD; t++) {
        // prefetch: idx for t+5, xg for t+2
        int nIa = 0, nIb = 0;
        if (t + 5 < TD) { nIa = x[(t + 5) * BD + b0]; nIb = x[(t + 5) * BD + b1]; }
        float nxa = g_table[I2a * G4 + wrow];
        float nxb = g_table[I2b * G4 + wrow];

        // gate pre-activation: xg + W_hh_row · h   (32 FFMA2)
        unsigned long long acc = XG0;
        const ulonglong2* hv2 = (const ulonglong2*)hbuf[grp][t & 1];
#pragma unroll
        for (int k2 = 0; k2 < HID / 2; k2++) {
            ulonglong2 hh = hv2[k2];
            acc = fma2(Wp[2 * k2 + 0], hh.x, acc);
            acc = fma2(Wp[2 * k2 + 1], hh.y, acc);
        }
        unsigned long long a2 = (gate == 2) ? tanh2(acc) : sigmoid2(acc);

        // gather i,f,g,o of this unit from the 4-lane quad
        unsigned long long iv = __shfl_sync(0xffffffffu, a2, lbase + 0);
        unsigned long long fv = __shfl_sync(0xffffffffu, a2, lbase + 1);
        unsigned long long gv = __shfl_sync(0xffffffffu, a2, lbase + 2);
        unsigned long long ov = __shfl_sync(0xffffffffu, a2, lbase + 3);

        c2 = fma2(fv, c2, mul2(iv, gv));                 // c = f*c + i*g
        unsigned long long hn = mul2(ov, tanh2(c2));     // h = o*tanh(c)

        if (gate == 0) {
            hbuf[grp][(t + 1) & 1][unit] = hn;           // write NEXT parity
            float ha, hb; upk(hn, ha, hb);
            hsA[t * HID + unit] = ha;
            hsB[t * HID + unit] = hb;
        }
        __syncthreads();

        XG0 = XG1; XG1 = pk(nxa, nxb);
        I2a = I3a; I2b = I3b; I3a = I4a; I3b = I4b; I4a = nIa; I4b = nIb;
    }
}

// ---------------- K2: fused FF head + softmax over T ------------------------
// One CTA per batch element b; thread handles timestep pair (2*tid, 2*tid+1).
// Logits never touch global memory; softmax over T via warp shfl + smem.
__global__ __launch_bounds__(256, 1)
void head_softmax_kernel(const float* __restrict__ W1, const float* __restrict__ b1,
                         const float* __restrict__ W2, const float* __restrict__ b2,
                         float* __restrict__ out) {
    __shared__ unsigned long long W1p[FF * HID];
    __shared__ unsigned long long W2p[NCLS * FF];
    __shared__ float b1s[FF], b2s[NCLS];
    __shared__ float wredm[8][NCLS], wreds[8][NCLS];

    int tid = threadIdx.x;
    for (int i = tid; i < FF * HID; i += 256) { float w = W1[i]; W1p[i] = pk(w, w); }
    if (tid < NCLS * FF) { float w = W2[tid]; W2p[tid] = pk(w, w); }
    if (tid < FF)   b1s[tid] = b1[tid];
    if (tid < NCLS) b2s[tid] = b2[tid];
    __syncthreads();

    int b  = blockIdx.x;
    int t0 = tid * 2;
    const float* hr = g_hs + ((size_t)b * TD + t0) * HID;

    unsigned long long h2[HID];
#pragma unroll
    for (int k4 = 0; k4 < HID / 4; k4++) {
        float4 u = ((const float4*)hr)[k4];
        float4 v = ((const float4*)(hr + HID))[k4];
        h2[k4 * 4 + 0] = pk(u.x, v.x);
        h2[k4 * 4 + 1] = pk(u.y, v.y);
        h2[k4 * 4 + 2] = pk(u.z, v.z);
        h2[k4 * 4 + 3] = pk(u.w, v.w);
    }

    unsigned long long z2[FF];
#pragma unroll
    for (int f = 0; f < FF; f++) {
        unsigned long long acc = pk(b1s[f], b1s[f]);
#pragma unroll
        for (int k = 0; k < HID; k++) acc = fma2(W1p[f * HID + k], h2[k], acc);
        float lo, hi; upk(acc, lo, hi);
        z2[f] = pk(fmaxf(lo, 0.f), fmaxf(hi, 0.f));
    }

    float va[NCLS], vb[NCLS];
#pragma unroll
    for (int c = 0; c < NCLS; c++) {
        unsigned long long acc = pk(b2s[c], b2s[c]);
#pragma unroll
        for (int k = 0; k < FF; k++) acc = fma2(W2p[c * FF + k], z2[k], acc);
        upk(acc, va[c], vb[c]);
    }

    // --- softmax over T (across the whole CTA) ---
    int wid = tid >> 5, lid = tid & 31;
    float vm[NCLS];
#pragma unroll
    for (int c = 0; c < NCLS; c++) vm[c] = fmaxf(va[c], vb[c]);
#pragma unroll
    for (int off = 16; off; off >>= 1)
#pragma unroll
        for (int c = 0; c < NCLS; c++)
            vm[c] = fmaxf(vm[c], __shfl_xor_sync(0xffffffffu, vm[c], off));
    if (lid == 0)
#pragma unroll
        for (int c = 0; c < NCLS; c++) wredm[wid][c] = vm[c];
    __syncthreads();
    float gmax[NCLS];
#pragma unroll
    for (int c = 0; c < NCLS; c++) {
        float m = wredm[0][c];
#pragma unroll
        for (int w = 1; w < 8; w++) m = fmaxf(m, wredm[w][c]);
        gmax[c] = m;
    }
    float sm[NCLS];
#pragma unroll
    for (int c = 0; c < NCLS; c++) {
        va[c] = __expf(va[c] - gmax[c]);
        vb[c] = __expf(vb[c] - gmax[c]);
        sm[c] = va[c] + vb[c];
    }
#pragma unroll
    for (int off = 16; off; off >>= 1)
#pragma unroll
        for (int c = 0; c < NCLS; c++)
            sm[c] += __shfl_xor_sync(0xffffffffu, sm[c], off);
    if (lid == 0)
#pragma unroll
        for (int c = 0; c < NCLS; c++) wreds[wid][c] = sm[c];
    __syncthreads();
    float inv[NCLS];
#pragma unroll
    for (int c = 0; c < NCLS; c++) {
        float s = wreds[0][c];
#pragma unroll
        for (int w = 1; w < 8; w++) s += wreds[w][c];
        inv[c] = 1.0f / s;
    }

    // out layout (T, B, NCLS)
    float* o0 = out + (size_t)t0 * BD * NCLS + (size_t)b * NCLS;
#pragma unroll
    for (int c = 0; c < NCLS; c++) o0[c] = va[c] * inv[c];
#pragma unroll
    for (int c = 0; c < NCLS; c++) o0[BD * NCLS + c] = vb[c] * inv[c];
}

// ---------------- launch -----------------------------------------------------
extern "C" void kernel_launch(void* const* d_in, const int* in_sizes, int n_in,
                              void* d_out, int out_size) {
    (void)in_sizes; (void)n_in; (void)out_size;
    const int*   x    = (const int*)  d_in[0];
    const float* emb  = (const float*)d_in[1];
    const float* W_ih = (const float*)d_in[2];
    const float* W_hh = (const float*)d_in[3];
    const float* b_ih = (const float*)d_in[4];
    const float* b_hh = (const float*)d_in[5];
    const float* W1   = (const float*)d_in[6];
    const float* b1   = (const float*)d_in[7];
    const float* W2   = (const float*)d_in[8];
    const float* b2   = (const float*)d_in[9];

    table_kernel<<<VOCAB, 128>>>(emb, W_ih, b_ih, b_hh);
    lstm_kernel<<<BD / 4, 256>>>(x, W_hh);
    head_softmax_kernel<<<BD, 256>>>(W1, b1, W2, b2, (float*)d_out);
}